// round 1
// baseline (speedup 1.0000x reference)
#include <cuda_runtime.h>
#include <cstdint>

#define E_ 8
#define D_ 1024
#define H_ 2816
#define T_ 16384
#define TM 128
#define TN 64
#define TK 16
#define MAXTILES (T_ / TM + E_)

// Scratch: intermediate h = silu(x@w1^T) * (x@w3^T), fp32 [T, H]
__device__ float g_h[(size_t)T_ * H_];

// Tile table (built on device each launch from num_tokens_per_expert)
__device__ int g_tile_row[MAXTILES];
__device__ int g_tile_cnt[MAXTILES];
__device__ int g_tile_e[MAXTILES];
__device__ int g_ntiles;

__global__ void setup_tiles(const int* __restrict__ counts) {
    int nt = 0, start = 0;
    for (int e = 0; e < E_; e++) {
        int c = counts[e];
        for (int off = 0; off < c; off += TM) {
            int rem = c - off;
            g_tile_row[nt] = start + off;
            g_tile_cnt[nt] = rem < TM ? rem : TM;
            g_tile_e[nt]   = e;
            nt++;
        }
        start += c;
    }
    g_ntiles = nt;
}

__device__ __forceinline__ float f2tf32(float x) {
    uint32_t u;
    asm("cvt.rna.tf32.f32 %0, %1;" : "=r"(u) : "f"(x));
    return __uint_as_float(u);
}

__device__ __forceinline__ void mma8(float* c, const uint32_t* a, uint32_t b0, uint32_t b1) {
    asm volatile(
        "mma.sync.aligned.m16n8k8.row.col.f32.tf32.tf32.f32 "
        "{%0,%1,%2,%3}, {%4,%5,%6,%7}, {%8,%9}, {%0,%1,%2,%3};\n"
        : "+f"(c[0]), "+f"(c[1]), "+f"(c[2]), "+f"(c[3])
        : "r"(a[0]), "r"(a[1]), "r"(a[2]), "r"(a[3]), "r"(b0), "r"(b1));
}

// Grouped GEMM: Out[t, n] = sum_k A[t, k] * W[e, n, k]   (W row n contiguous in k)
// NMAT==2: computes with W0 (w1) and W1 (w3), epilogue = silu(c0)*c1 -> g_h
// NMAT==1: computes with W0 (w2), epilogue = plain store -> Out
template <int NMAT>
__global__ __launch_bounds__(256, 2) void grouped_gemm(
    const float* __restrict__ A,   // [T, KTOT] or nullptr -> g_h
    const float* __restrict__ W0,  // [E, NTOT, KTOT]
    const float* __restrict__ W1,  // [E, NTOT, KTOT] or unused
    float* __restrict__ Out,       // [T, NTOT] or nullptr -> g_h
    int KTOT, int NTOT) {
    if ((int)blockIdx.y >= g_ntiles) return;
    const int tile = blockIdx.y;
    const int row0 = g_tile_row[tile];
    const int cnt  = g_tile_cnt[tile];
    const int e    = g_tile_e[tile];
    const int nb   = blockIdx.x * TN;

    const float* Ap = A ? A : (const float*)g_h;
    float* Op = Out ? Out : g_h;

    __shared__ float sA[2][TK][TM + 8];          // stride 136 (mod32 = 8 -> conflict-free frags)
    __shared__ float sB[2][NMAT][TK][TN + 8];    // stride 72  (mod32 = 8)

    const int t    = threadIdx.x;
    const int lrow = t >> 2;          // 0..63
    const int lk4  = (t & 3) << 2;    // 0,4,8,12

    const int warp = t >> 5;
    const int lane = t & 31;
    const int wm = (warp >> 1) * 32;  // warp row block (4 warps along M)
    const int wn = (warp & 1) * 32;   // warp col block (2 warps along N)
    const int g  = lane >> 2;         // groupID 0..7
    const int tg = lane & 3;          // thread in group

    const float* Wp0 = W0 + ((size_t)e * NTOT + nb + lrow) * KTOT + lk4;
    const float* Wp1 = (NMAT == 2) ? (W1 + ((size_t)e * NTOT + nb + lrow) * KTOT + lk4) : Wp0;

    const float* Ar0 = Ap + (size_t)(row0 + lrow) * KTOT + lk4;
    const float* Ar1 = Ap + (size_t)(row0 + lrow + 64) * KTOT + lk4;
    const bool av0 = lrow < cnt;
    const bool av1 = (lrow + 64) < cnt;

    float4 ra0, ra1, rb0, rb1;

    auto prefetch = [&](int kt) {
        const float4 z = make_float4(0.f, 0.f, 0.f, 0.f);
        ra0 = av0 ? *(const float4*)(Ar0 + (size_t)kt * TK) : z;
        ra1 = av1 ? *(const float4*)(Ar1 + (size_t)kt * TK) : z;
        rb0 = *(const float4*)(Wp0 + (size_t)kt * TK);
        if (NMAT == 2) rb1 = *(const float4*)(Wp1 + (size_t)kt * TK);
    };
    auto commit = [&](int buf) {
        sA[buf][lk4 + 0][lrow] = f2tf32(ra0.x);
        sA[buf][lk4 + 1][lrow] = f2tf32(ra0.y);
        sA[buf][lk4 + 2][lrow] = f2tf32(ra0.z);
        sA[buf][lk4 + 3][lrow] = f2tf32(ra0.w);
        sA[buf][lk4 + 0][lrow + 64] = f2tf32(ra1.x);
        sA[buf][lk4 + 1][lrow + 64] = f2tf32(ra1.y);
        sA[buf][lk4 + 2][lrow + 64] = f2tf32(ra1.z);
        sA[buf][lk4 + 3][lrow + 64] = f2tf32(ra1.w);
        sB[buf][0][lk4 + 0][lrow] = f2tf32(rb0.x);
        sB[buf][0][lk4 + 1][lrow] = f2tf32(rb0.y);
        sB[buf][0][lk4 + 2][lrow] = f2tf32(rb0.z);
        sB[buf][0][lk4 + 3][lrow] = f2tf32(rb0.w);
        if (NMAT == 2) {
            sB[buf][NMAT - 1][lk4 + 0][lrow] = f2tf32(rb1.x);
            sB[buf][NMAT - 1][lk4 + 1][lrow] = f2tf32(rb1.y);
            sB[buf][NMAT - 1][lk4 + 2][lrow] = f2tf32(rb1.z);
            sB[buf][NMAT - 1][lk4 + 3][lrow] = f2tf32(rb1.w);
        }
    };

    float acc[NMAT][2][4][4];
    #pragma unroll
    for (int m = 0; m < NMAT; m++)
        #pragma unroll
        for (int mt = 0; mt < 2; mt++)
            #pragma unroll
            for (int nt = 0; nt < 4; nt++)
                #pragma unroll
                for (int r = 0; r < 4; r++) acc[m][mt][nt][r] = 0.f;

    const int KT = KTOT / TK;
    prefetch(0);
    commit(0);
    __syncthreads();

    for (int kt = 0; kt < KT; kt++) {
        const int buf = kt & 1;
        if (kt + 1 < KT) prefetch(kt + 1);

        #pragma unroll
        for (int kk = 0; kk < TK; kk += 8) {
            uint32_t a[2][4];
            #pragma unroll
            for (int mt = 0; mt < 2; mt++) {
                const int r0 = wm + mt * 16 + g;
                a[mt][0] = __float_as_uint(sA[buf][kk + tg][r0]);
                a[mt][1] = __float_as_uint(sA[buf][kk + tg][r0 + 8]);
                a[mt][2] = __float_as_uint(sA[buf][kk + tg + 4][r0]);
                a[mt][3] = __float_as_uint(sA[buf][kk + tg + 4][r0 + 8]);
            }
            #pragma unroll
            for (int m = 0; m < NMAT; m++) {
                #pragma unroll
                for (int nt = 0; nt < 4; nt++) {
                    const int c0 = wn + nt * 8 + g;
                    uint32_t b0 = __float_as_uint(sB[buf][m][kk + tg][c0]);
                    uint32_t b1 = __float_as_uint(sB[buf][m][kk + tg + 4][c0]);
                    mma8(acc[m][0][nt], a[0], b0, b1);
                    mma8(acc[m][1][nt], a[1], b0, b1);
                }
            }
        }

        if (kt + 1 < KT) commit((kt + 1) & 1);
        __syncthreads();
    }

    // Epilogue
    #pragma unroll
    for (int mt = 0; mt < 2; mt++) {
        #pragma unroll
        for (int nt = 0; nt < 4; nt++) {
            #pragma unroll
            for (int r = 0; r < 4; r++) {
                const int row = wm + mt * 16 + g + ((r >> 1) << 3);
                if (row < cnt) {
                    const int col = nb + wn + nt * 8 + tg * 2 + (r & 1);
                    if (NMAT == 2) {
                        const float h1 = acc[0][mt][nt][r];
                        const float h3 = acc[NMAT - 1][mt][nt][r];
                        const float s = h1 * (1.f / (1.f + __expf(-h1)));
                        Op[(size_t)(row0 + row) * NTOT + col] = s * h3;
                    } else {
                        Op[(size_t)(row0 + row) * NTOT + col] = acc[0][mt][nt][r];
                    }
                }
            }
        }
    }
}

extern "C" void kernel_launch(void* const* d_in, const int* in_sizes, int n_in,
                              void* d_out, int out_size) {
    const float* x  = (const float*)d_in[0];
    const float* w1 = (const float*)d_in[1];
    const float* w2 = (const float*)d_in[2];
    const float* w3 = (const float*)d_in[3];
    const int*  cnt = (const int*)d_in[4];
    float* out = (float*)d_out;

    setup_tiles<<<1, 1>>>(cnt);
    cudaMemsetAsync(d_out, 0, (size_t)T_ * D_ * sizeof(float));

    // h = silu(x @ w1^T) * (x @ w3^T)  -> g_h  [T, H]
    grouped_gemm<2><<<dim3(H_ / TN, MAXTILES), 256>>>(x, w1, w3, nullptr, D_, H_);
    // out = h @ w2^T  [T, D]
    grouped_gemm<1><<<dim3(D_ / TN, MAXTILES), 256>>>(nullptr, w2, nullptr, out, H_, D_);
}

// round 7
// speedup vs baseline: 1.4274x; 1.4274x over previous
#include <cuda_runtime.h>
#include <cstdint>

#define E_ 8
#define D_ 1024
#define H_ 2816
#define T_ 16384
#define TM 128
#define TNB 256            // unified B rows per stage
#define TK 32
#define NSTAGE 3
#define MAXTILES (T_ / TM + E_)

// Scratch: h = silu(x@w1^T) * (x@w3^T), fp32 [T, H]
__device__ float g_h[(size_t)T_ * H_];

__device__ int g_tile_row[MAXTILES];
__device__ int g_tile_cnt[MAXTILES];
__device__ int g_tile_e[MAXTILES];
__device__ int g_ntiles;

__global__ void setup_tiles(const int* __restrict__ counts) {
    int nt = 0, start = 0;
    for (int e = 0; e < E_; e++) {
        int c = counts[e];
        for (int off = 0; off < c; off += TM) {
            int rem = c - off;
            g_tile_row[nt] = start + off;
            g_tile_cnt[nt] = rem < TM ? rem : TM;
            g_tile_e[nt]   = e;
            nt++;
        }
        start += c;
    }
    g_ntiles = nt;
}

// ---- helpers ----
__device__ __forceinline__ uint32_t smem_u32(const void* p) {
    uint32_t a;
    asm("{ .reg .u64 t; cvta.to.shared.u64 t, %1; cvt.u32.u64 %0, t; }" : "=r"(a) : "l"(p));
    return a;
}
__device__ __forceinline__ uint32_t f2tf32(float x) {
    uint32_t u;
    asm("cvt.rna.tf32.f32 %0, %1;" : "=r"(u) : "f"(x));
    return u;
}
__device__ __forceinline__ void cpa16(uint32_t dst, const float* src, int sz) {
    asm volatile("cp.async.cg.shared.global [%0], [%1], 16, %2;"
                 :: "r"(dst), "l"(src), "r"(sz));
}
__device__ __forceinline__ void cp_commit() {
    asm volatile("cp.async.commit_group;" ::: "memory");
}
template <int N>
__device__ __forceinline__ void cp_wait() {
    asm volatile("cp.async.wait_group %0;" :: "n"(N) : "memory");
}
__device__ __forceinline__ void mma8(float* c, const uint32_t* a, uint32_t b0, uint32_t b1) {
    asm volatile(
        "mma.sync.aligned.m16n8k8.row.col.f32.tf32.tf32.f32 "
        "{%0,%1,%2,%3}, {%4,%5,%6,%7}, {%8,%9}, {%0,%1,%2,%3};\n"
        : "+f"(c[0]), "+f"(c[1]), "+f"(c[2]), "+f"(c[3])
        : "r"(a[0]), "r"(a[1]), "r"(a[2]), "r"(a[3]), "r"(b0), "r"(b1));
}

// smem geometry (floats)
#define A_STRIDE 36
#define B_STRIDE 36
#define A_BYTES (TM * A_STRIDE * 4)            // 18432
#define B_BYTES (TNB * B_STRIDE * 4)           // 36864
#define STG_BYTES (A_BYTES + B_BYTES)          // 55296
#define SMEM_TOTAL (NSTAGE * STG_BYTES)        // 165888

// NMAT==2: B rows [0,128)=w1 slice, [128,256)=w3 slice; out cols = 128 (silu fuse)
// NMAT==1: B rows = w2 slice; out cols = 256
template <int NMAT>
__global__ __launch_bounds__(256, 1) void moe_tf32(
    const float* __restrict__ A,   // [T, KTOT] or nullptr -> g_h
    const float* __restrict__ W0,  // [E, NW, KTOT]
    const float* __restrict__ W1,  // [E, NW, KTOT] (NMAT==2)
    float* __restrict__ Out,       // [T, OUTW] or nullptr -> g_h
    int KTOT, int OUTW, int KT) {
    if ((int)blockIdx.x >= g_ntiles) return;
    const int tile = blockIdx.x;
    const int row0 = g_tile_row[tile];
    const int cnt  = g_tile_cnt[tile];
    const int e    = g_tile_e[tile];
    const int nb   = blockIdx.y * (NMAT == 2 ? 128 : 256);  // weight-row / out-col base
    const int NW   = OUTW;  // weight rows per expert == output width

    const float* Ap = A ? A : (const float*)g_h;
    float* Op = Out ? Out : g_h;

    extern __shared__ char smem[];
    const uint32_t sb = smem_u32(smem);

    const int t    = threadIdx.x;
    const int warp = t >> 5;
    const int lane = t & 31;
    const int g    = lane >> 2;   // 0..7
    const int tg   = lane & 3;    // 0..3
    const int wm   = (warp & 1) * 64;
    const int wn   = (warp >> 1) * 64;

    // ---- loader maps ----
    const int lr = t >> 3;        // base row 0..31
    const int lc = t & 7;         // 16B segment 0..7
    const float* a_base = Ap + (size_t)(row0 + lr) * KTOT + lc * 4;
    const float* b0_base = W0 + ((size_t)e * NW + nb + lr) * KTOT + lc * 4;
    const float* b1_base = (NMAT == 2)
        ? (W1 + ((size_t)e * NW + nb + lr) * KTOT + lc * 4)
        : (b0_base + (size_t)128 * KTOT);
    const uint32_t a_dst = sb + (lr * A_STRIDE + lc * 4) * 4;
    const uint32_t b_dst = sb + A_BYTES + (lr * B_STRIDE + lc * 4) * 4;

    auto issue = [&](int kt) {
        const uint32_t so = (kt % NSTAGE) * STG_BYTES;
        const size_t ko = (size_t)kt * TK;
        #pragma unroll
        for (int j = 0; j < 4; j++) {
            const int sz = (lr + 32 * j < cnt) ? 16 : 0;
            cpa16(a_dst + so + j * 32 * A_STRIDE * 4, a_base + (size_t)32 * j * KTOT + ko, sz);
        }
        #pragma unroll
        for (int j = 0; j < 4; j++)
            cpa16(b_dst + so + j * 32 * B_STRIDE * 4, b0_base + (size_t)32 * j * KTOT + ko, 16);
        #pragma unroll
        for (int j = 0; j < 4; j++)
            cpa16(b_dst + so + (128 + 32 * j) * B_STRIDE * 4, b1_base + (size_t)32 * j * KTOT + ko, 16);
        cp_commit();
    };

    float acc[4][8][4];
    #pragma unroll
    for (int mt = 0; mt < 4; mt++)
        #pragma unroll
        for (int nt = 0; nt < 8; nt++)
            #pragma unroll
            for (int r = 0; r < 4; r++) acc[mt][nt][r] = 0.f;

    auto domma = [&](int kt) {
        const float* sA = (const float*)(smem + (kt % NSTAGE) * STG_BYTES);
        const float* sB = (const float*)(smem + (kt % NSTAGE) * STG_BYTES + A_BYTES);
        #pragma unroll
        for (int kk = 0; kk < TK; kk += 8) {
            uint32_t a[4][4];
            #pragma unroll
            for (int mt = 0; mt < 4; mt++) {
                const int r0 = wm + mt * 16 + g;
                a[mt][0] = f2tf32(sA[r0 * A_STRIDE + kk + tg]);
                a[mt][1] = f2tf32(sA[(r0 + 8) * A_STRIDE + kk + tg]);
                a[mt][2] = f2tf32(sA[r0 * A_STRIDE + kk + tg + 4]);
                a[mt][3] = f2tf32(sA[(r0 + 8) * A_STRIDE + kk + tg + 4]);
            }
            uint32_t b[8][2];
            #pragma unroll
            for (int nt = 0; nt < 8; nt++) {
                const int c0 = wn + nt * 8 + g;
                b[nt][0] = f2tf32(sB[c0 * B_STRIDE + kk + tg]);
                b[nt][1] = f2tf32(sB[c0 * B_STRIDE + kk + tg + 4]);
            }
            #pragma unroll
            for (int mt = 0; mt < 4; mt++)
                #pragma unroll
                for (int nt = 0; nt < 8; nt++)
                    mma8(acc[mt][nt], a[mt], b[nt][0], b[nt][1]);
        }
    };

    // ---- pipeline ----
    issue(0);
    issue(1);
    for (int kt = 0; kt < KT; kt++) {
        if (kt < KT - 1) cp_wait<1>(); else cp_wait<0>();
        __syncthreads();
        if (kt + 2 < KT) issue(kt + 2);
        domma(kt);
    }
    __syncthreads();   // all warps done with mma before smem reuse

    // ---- epilogue ----
    if (NMAT == 2) {
        float* xbuf = (float*)smem;  // 128 x 132 fp32 = 67584 B
        if (wn >= 128) {
            const int wnl = wn - 128;
            #pragma unroll
            for (int mt = 0; mt < 4; mt++)
                #pragma unroll
                for (int nt = 0; nt < 8; nt++)
                    #pragma unroll
                    for (int rp = 0; rp < 2; rp++) {
                        const int row = wm + mt * 16 + g + 8 * rp;
                        const int col = wnl + nt * 8 + tg * 2;
                        *(float2*)&xbuf[row * 132 + col] =
                            make_float2(acc[mt][nt][rp * 2], acc[mt][nt][rp * 2 + 1]);
                    }
        }
        __syncthreads();
        if (wn < 128) {
            #pragma unroll
            for (int mt = 0; mt < 4; mt++) {
                #pragma unroll
                for (int rp = 0; rp < 2; rp++) {
                    const int row = wm + mt * 16 + g + 8 * rp;
                    if (row < cnt) {
                        float* op = Op + (size_t)(row0 + row) * OUTW + nb;
                        #pragma unroll
                        for (int nt = 0; nt < 8; nt++) {
                            const int col = wn + nt * 8 + tg * 2;
                            const float2 h3 = *(const float2*)&xbuf[row * 132 + col];
                            const float h1a = acc[mt][nt][rp * 2];
                            const float h1b = acc[mt][nt][rp * 2 + 1];
                            const float sa = h1a * (1.f / (1.f + __expf(-h1a)));
                            const float sbv = h1b * (1.f / (1.f + __expf(-h1b)));
                            *(float2*)&op[col] = make_float2(sa * h3.x, sbv * h3.y);
                        }
                    }
                }
            }
        }
    } else {
        #pragma unroll
        for (int mt = 0; mt < 4; mt++) {
            #pragma unroll
            for (int rp = 0; rp < 2; rp++) {
                const int row = wm + mt * 16 + g + 8 * rp;
                if (row < cnt) {
                    float* op = Op + (size_t)(row0 + row) * OUTW + nb;
                    #pragma unroll
                    for (int nt = 0; nt < 8; nt++) {
                        const int col = wn + nt * 8 + tg * 2;
                        *(float2*)&op[col] =
                            make_float2(acc[mt][nt][rp * 2], acc[mt][nt][rp * 2 + 1]);
                    }
                }
            }
        }
    }
}

extern "C" void kernel_launch(void* const* d_in, const int* in_sizes, int n_in,
                              void* d_out, int out_size) {
    const float* x  = (const float*)d_in[0];
    const float* w1 = (const float*)d_in[1];
    const float* w2 = (const float*)d_in[2];
    const float* w3 = (const float*)d_in[3];
    const int*  cnt = (const int*)d_in[4];
    float* out = (float*)d_out;

    cudaFuncSetAttribute(moe_tf32<2>, cudaFuncAttributeMaxDynamicSharedMemorySize, SMEM_TOTAL);
    cudaFuncSetAttribute(moe_tf32<1>, cudaFuncAttributeMaxDynamicSharedMemorySize, SMEM_TOTAL);

    setup_tiles<<<1, 1>>>(cnt);
    cudaMemsetAsync(d_out, 0, (size_t)T_ * D_ * sizeof(float));

    // h = silu(x @ w1^T) * (x @ w3^T) -> g_h  [T, H]
    moe_tf32<2><<<dim3(MAXTILES, H_ / 128), 256, SMEM_TOTAL>>>(
        x, w1, w3, nullptr, D_, H_, D_ / TK);
    // out = h @ w2^T  [T, D]
    moe_tf32<1><<<dim3(MAXTILES, D_ / 256), 256, SMEM_TOTAL>>>(
        nullptr, w2, nullptr, out, H_, D_, H_ / TK);
}

// round 11
// speedup vs baseline: 2.3027x; 1.6133x over previous
#include <cuda_runtime.h>
#include <cuda_fp16.h>
#include <cstdint>

#define E_ 8
#define D_ 1024
#define H_ 2816
#define T_ 16384
#define TM 128
#define TK 32
#define NSTAGE 4
#define MAXTILES (T_ / TM + E_)

#define WSZ ((size_t)E_ * H_ * D_)   // 23,068,672 (same for w2: E*D*H)

// fp16 copies of inputs + intermediate
__device__ __half g_w1h[WSZ];
__device__ __half g_w3h[WSZ];
__device__ __half g_w2h[WSZ];
__device__ __half g_xh[(size_t)T_ * D_];
__device__ __half g_h[(size_t)T_ * H_];

__device__ int g_tile_row[MAXTILES];
__device__ int g_tile_cnt[MAXTILES];
__device__ int g_tile_e[MAXTILES];
__device__ int g_ntiles;

__global__ void setup_tiles(const int* __restrict__ counts) {
    int nt = 0, start = 0;
    for (int e = 0; e < E_; e++) {
        int c = counts[e];
        for (int off = 0; off < c; off += TM) {
            int rem = c - off;
            g_tile_row[nt] = start + off;
            g_tile_cnt[nt] = rem < TM ? rem : TM;
            g_tile_e[nt]   = e;
            nt++;
        }
        start += c;
    }
    g_ntiles = nt;
}

__device__ __forceinline__ void conv_loop(const float* __restrict__ s, __half* __restrict__ d,
                                          size_t n4, size_t tid, size_t stride) {
    const float4* s4 = (const float4*)s;
    uint2* d4 = (uint2*)d;
    for (size_t i = tid; i < n4; i += stride) {
        float4 v = s4[i];
        __half2 h0 = __floats2half2_rn(v.x, v.y);
        __half2 h1 = __floats2half2_rn(v.z, v.w);
        uint2 u;
        u.x = *(uint32_t*)&h0;
        u.y = *(uint32_t*)&h1;
        d4[i] = u;
    }
}

__global__ void convert_all(const float* __restrict__ x, const float* __restrict__ w1,
                            const float* __restrict__ w2, const float* __restrict__ w3) {
    const size_t tid = (size_t)blockIdx.x * blockDim.x + threadIdx.x;
    const size_t stride = (size_t)gridDim.x * blockDim.x;
    conv_loop(x,  g_xh,  (size_t)T_ * D_ / 4, tid, stride);
    conv_loop(w1, g_w1h, WSZ / 4, tid, stride);
    conv_loop(w3, g_w3h, WSZ / 4, tid, stride);
    conv_loop(w2, g_w2h, WSZ / 4, tid, stride);
}

// ---- helpers ----
__device__ __forceinline__ uint32_t smem_u32(const void* p) {
    uint32_t a;
    asm("{ .reg .u64 t; cvta.to.shared.u64 t, %1; cvt.u32.u64 %0, t; }" : "=r"(a) : "l"(p));
    return a;
}
__device__ __forceinline__ void cpa16(uint32_t dst, const void* src, int sz) {
    asm volatile("cp.async.cg.shared.global [%0], [%1], 16, %2;"
                 :: "r"(dst), "l"(src), "r"(sz));
}
__device__ __forceinline__ void cp_commit() {
    asm volatile("cp.async.commit_group;" ::: "memory");
}
template <int N>
__device__ __forceinline__ void cp_wait() {
    asm volatile("cp.async.wait_group %0;" :: "n"(N) : "memory");
}
__device__ __forceinline__ void mma16(float* c, const uint32_t* a, uint32_t b0, uint32_t b1) {
    asm volatile(
        "mma.sync.aligned.m16n8k16.row.col.f32.f16.f16.f32 "
        "{%0,%1,%2,%3}, {%4,%5,%6,%7}, {%8,%9}, {%0,%1,%2,%3};\n"
        : "+f"(c[0]), "+f"(c[1]), "+f"(c[2]), "+f"(c[3])
        : "r"(a[0]), "r"(a[1]), "r"(a[2]), "r"(a[3]), "r"(b0), "r"(b1));
}

// smem geometry: halves, row stride 40 halves (80B; word stride 20 -> LDS conflict-free)
#define RSTR 40
#define A_BYTES (TM * RSTR * 2)          // 10240
#define B_BYTES (256 * RSTR * 2)         // 20480
#define STG_BYTES (A_BYTES + B_BYTES)    // 30720
#define SMEM_TOTAL (NSTAGE * STG_BYTES)  // 122880

// NMAT==2: A=g_xh, B rows [0,128)=w1, [128,256)=w3; epilogue silu -> g_h (fp16), 128 cols
// NMAT==1: A=g_h, B rows = w2; epilogue -> Out (fp32), 256 cols
template <int NMAT>
__global__ __launch_bounds__(256, 1) void moe_fp16(
    float* __restrict__ Out, int KTOT, int OUTW, int KT) {
    if ((int)blockIdx.x >= g_ntiles) return;
    const int tile = blockIdx.x;
    const int row0 = g_tile_row[tile];
    const int cnt  = g_tile_cnt[tile];
    const int e    = g_tile_e[tile];
    const int nb   = blockIdx.y * (NMAT == 2 ? 128 : 256);

    const __half* Ap = (NMAT == 2) ? g_xh : g_h;
    const __half* B0 = (NMAT == 2) ? (g_w1h + ((size_t)e * OUTW + nb) * KTOT)
                                   : (g_w2h + ((size_t)e * OUTW + nb) * KTOT);
    const __half* B1 = (NMAT == 2) ? (g_w3h + ((size_t)e * OUTW + nb) * KTOT)
                                   : (g_w2h + ((size_t)e * OUTW + nb + 128) * KTOT);

    extern __shared__ char smem[];
    const uint32_t sb = smem_u32(smem);

    const int t    = threadIdx.x;
    const int warp = t >> 5;
    const int lane = t & 31;
    const int g    = lane >> 2;   // 0..7
    const int tg   = lane & 3;    // 0..3
    const int wm   = (warp & 1) * 64;
    const int wn   = (warp >> 1) * 64;

    // loader map: lr = row 0..63 (+64 for second half), ls = 16B segment 0..3
    const int lr = t >> 2;
    const int ls = t & 3;
    const __half* a_src0 = Ap + (size_t)(row0 + lr) * KTOT + ls * 8;
    const __half* a_src1 = Ap + (size_t)(row0 + lr + 64) * KTOT + ls * 8;
    const __half* b_src[4] = {
        B0 + (size_t)lr * KTOT + ls * 8,
        B0 + (size_t)(lr + 64) * KTOT + ls * 8,
        B1 + (size_t)lr * KTOT + ls * 8,
        B1 + (size_t)(lr + 64) * KTOT + ls * 8};
    const uint32_t a_dst = sb + lr * (RSTR * 2) + ls * 16;
    const uint32_t b_dst = sb + A_BYTES + lr * (RSTR * 2) + ls * 16;
    const int sz0 = (lr < cnt) ? 16 : 0;
    const int sz1 = (lr + 64 < cnt) ? 16 : 0;

    auto issue = [&](int kt) {
        const uint32_t so = (kt % NSTAGE) * STG_BYTES;
        const size_t ko = (size_t)kt * TK;
        cpa16(a_dst + so, a_src0 + ko, sz0);
        cpa16(a_dst + so + 64 * RSTR * 2, a_src1 + ko, sz1);
        #pragma unroll
        for (int j = 0; j < 4; j++)
            cpa16(b_dst + so + j * 64 * RSTR * 2, b_src[j] + ko, 16);
        cp_commit();
    };

    float acc[4][8][4];
    #pragma unroll
    for (int mt = 0; mt < 4; mt++)
        #pragma unroll
        for (int nt = 0; nt < 8; nt++)
            #pragma unroll
            for (int r = 0; r < 4; r++) acc[mt][nt][r] = 0.f;

    auto domma = [&](int kt) {
        const uint32_t* sA = (const uint32_t*)(smem + (kt % NSTAGE) * STG_BYTES);
        const uint32_t* sB = (const uint32_t*)(smem + (kt % NSTAGE) * STG_BYTES + A_BYTES);
        #pragma unroll
        for (int kk2 = 0; kk2 < TK / 2; kk2 += 8) {   // kk2 = k/2 word offset: 0, 8
            uint32_t a[4][4];
            #pragma unroll
            for (int mt = 0; mt < 4; mt++) {
                const int r0 = wm + mt * 16 + g;
                a[mt][0] = sA[r0 * 20 + kk2 + tg];
                a[mt][1] = sA[(r0 + 8) * 20 + kk2 + tg];
                a[mt][2] = sA[r0 * 20 + kk2 + 4 + tg];
                a[mt][3] = sA[(r0 + 8) * 20 + kk2 + 4 + tg];
            }
            uint32_t b[8][2];
            #pragma unroll
            for (int nt = 0; nt < 8; nt++) {
                const int c0 = wn + nt * 8 + g;
                b[nt][0] = sB[c0 * 20 + kk2 + tg];
                b[nt][1] = sB[c0 * 20 + kk2 + 4 + tg];
            }
            #pragma unroll
            for (int mt = 0; mt < 4; mt++)
                #pragma unroll
                for (int nt = 0; nt < 8; nt++)
                    mma16(acc[mt][nt], a[mt], b[nt][0], b[nt][1]);
        }
    };

    // ---- pipeline (NSTAGE-1 in flight) ----
    issue(0);
    issue(1);
    issue(2);
    for (int kt = 0; kt < KT; kt++) {
        if (kt + 2 < KT) cp_wait<2>();
        else if (kt + 1 < KT) cp_wait<1>();
        else cp_wait<0>();
        __syncthreads();
        if (kt + 3 < KT) issue(kt + 3);
        domma(kt);
    }
    __syncthreads();

    // ---- epilogue ----
    if (NMAT == 2) {
        float* xbuf = (float*)smem;  // 128 x 132 fp32 = 67584 B < SMEM_TOTAL
        if (wn >= 128) {
            const int wnl = wn - 128;
            #pragma unroll
            for (int mt = 0; mt < 4; mt++)
                #pragma unroll
                for (int nt = 0; nt < 8; nt++)
                    #pragma unroll
                    for (int rp = 0; rp < 2; rp++) {
                        const int row = wm + mt * 16 + g + 8 * rp;
                        const int col = wnl + nt * 8 + tg * 2;
                        *(float2*)&xbuf[row * 132 + col] =
                            make_float2(acc[mt][nt][rp * 2], acc[mt][nt][rp * 2 + 1]);
                    }
        }
        __syncthreads();
        if (wn < 128) {
            #pragma unroll
            for (int mt = 0; mt < 4; mt++) {
                #pragma unroll
                for (int rp = 0; rp < 2; rp++) {
                    const int row = wm + mt * 16 + g + 8 * rp;
                    if (row < cnt) {
                        __half* op = g_h + (size_t)(row0 + row) * OUTW + nb;
                        #pragma unroll
                        for (int nt = 0; nt < 8; nt++) {
                            const int col = wn + nt * 8 + tg * 2;
                            const float2 h3 = *(const float2*)&xbuf[row * 132 + col];
                            const float h1a = acc[mt][nt][rp * 2];
                            const float h1b = acc[mt][nt][rp * 2 + 1];
                            const float sa = h1a * (1.f / (1.f + __expf(-h1a)));
                            const float sbv = h1b * (1.f / (1.f + __expf(-h1b)));
                            __half2 hv = __floats2half2_rn(sa * h3.x, sbv * h3.y);
                            *(__half2*)&op[col] = hv;
                        }
                    }
                }
            }
        }
    } else {
        #pragma unroll
        for (int mt = 0; mt < 4; mt++) {
            #pragma unroll
            for (int rp = 0; rp < 2; rp++) {
                const int row = wm + mt * 16 + g + 8 * rp;
                if (row < cnt) {
                    float* op = Out + (size_t)(row0 + row) * OUTW + nb;
                    #pragma unroll
                    for (int nt = 0; nt < 8; nt++) {
                        const int col = wn + nt * 8 + tg * 2;
                        *(float2*)&op[col] =
                            make_float2(acc[mt][nt][rp * 2], acc[mt][nt][rp * 2 + 1]);
                    }
                }
            }
        }
    }
}

extern "C" void kernel_launch(void* const* d_in, const int* in_sizes, int n_in,
                              void* d_out, int out_size) {
    const float* x  = (const float*)d_in[0];
    const float* w1 = (const float*)d_in[1];
    const float* w2 = (const float*)d_in[2];
    const float* w3 = (const float*)d_in[3];
    const int*  cnt = (const int*)d_in[4];
    float* out = (float*)d_out;

    cudaFuncSetAttribute(moe_fp16<2>, cudaFuncAttributeMaxDynamicSharedMemorySize, SMEM_TOTAL);
    cudaFuncSetAttribute(moe_fp16<1>, cudaFuncAttributeMaxDynamicSharedMemorySize, SMEM_TOTAL);

    setup_tiles<<<1, 1>>>(cnt);
    convert_all<<<2048, 256>>>(x, w1, w2, w3);
    cudaMemsetAsync(d_out, 0, (size_t)T_ * D_ * sizeof(float));

    // h = silu(x @ w1^T) * (x @ w3^T) -> g_h (fp16) [T, H]
    moe_fp16<2><<<dim3(MAXTILES, H_ / 128), 256, SMEM_TOTAL>>>(nullptr, D_, H_, D_ / TK);
    // out = h @ w2^T  [T, D]
    moe_fp16<1><<<dim3(MAXTILES, D_ / 256), 256, SMEM_TOTAL>>>(out, H_, D_, H_ / TK);
}